// round 13
// baseline (speedup 1.0000x reference)
#include <cuda_runtime.h>
#include <cuda_bf16.h>
#include <math.h>
#include <stdint.h>

#define BB 16
#define NN 2304
#define HH 48
#define CIN 256
#define GM 1024

__device__ float  g_xf[BB*NN*64];
__device__ float  g_x2[BB*NN];
__device__ float2 g_tsp[64*32];
__device__ float  g_c0[64], g_c1[64], g_c2[64];
__device__ float  g_P[GM*NN];
__device__ float  g_M[BB*64*64];
__device__ float  g_colsum[GM], g_S[GM], g_pisum[GM];
__device__ float  g_T[HH*HH];
__device__ float  g_rcol[NN];
/* row-major bf16 split operands */
__device__ __nv_bfloat16 g_Ph[GM*NN], g_Pl[GM*NN];
__device__ __nv_bfloat16 g_Bh[NN*NN], g_Bl[NN*NN];   /* opB[m][n] = Amask[n][m] */
__device__ __nv_bfloat16 g_Yh[GM*NN], g_Yl[GM*NN];

/* ---------------- helpers ---------------- */
__device__ __forceinline__ unsigned int smem_u32(const void* p) {
    unsigned int a;
    asm("{ .reg .u64 t; cvta.to.shared.u64 t, %1; cvt.u32.u64 %0, t; }" : "=r"(a) : "l"(p));
    return a;
}
#define CP16(sa, gp) asm volatile("cp.async.cg.shared.global [%0], [%1], 16;" :: "r"(sa), "l"(gp) : "memory")
#define CP_COMMIT()  asm volatile("cp.async.commit_group;" ::: "memory")
#define CP_WAIT0()   asm volatile("cp.async.wait_group 0;" ::: "memory")
#define LDSM4(R0,R1,R2,R3,A) \
    asm volatile("ldmatrix.sync.aligned.m8n8.x4.shared.b16 {%0,%1,%2,%3}, [%4];" \
                 : "=r"(R0),"=r"(R1),"=r"(R2),"=r"(R3) : "r"(A))

__device__ __forceinline__ void mma16816(float* c, const unsigned* a, const unsigned* b) {
    asm volatile("mma.sync.aligned.m16n8k16.row.col.f32.bf16.bf16.f32 "
                 "{%0,%1,%2,%3}, {%4,%5,%6,%7}, {%8,%9}, {%0,%1,%2,%3};"
                 : "+f"(c[0]), "+f"(c[1]), "+f"(c[2]), "+f"(c[3])
                 : "r"(a[0]), "r"(a[1]), "r"(a[2]), "r"(a[3]), "r"(b[0]), "r"(b[1]));
}

/* ---------------- small kernels ---------------- */
__global__ void k_zero() {
    int i = blockIdx.x*256 + threadIdx.x;
    if (i < BB*64*64) g_M[i] = 0.f;
    else { int j = i - BB*64*64;
        if (j < GM) g_colsum[j] = 0.f;
        else if (j < 2*GM) g_S[j-GM] = 0.f;
        else if (j < 3*GM) g_pisum[j-2*GM] = 0.f; }
}

__global__ void k_tmpl(const float* __restrict__ clus, const float* __restrict__ pi,
                       const float* __restrict__ cov, const float* __restrict__ nts,
                       const float* __restrict__ ntb) {
    __shared__ float ts[64][65];
    int tid = threadIdx.x, w = tid>>5, lane = tid&31;
    for (int q = 0; q < 8; q++) {
        int k = w*8 + q;
        float v0 = clus[k*64+lane], v1 = clus[k*64+lane+32];
        float s = v0+v1;
        for (int o=16;o>0;o>>=1) s += __shfl_xor_sync(~0u,s,o);
        float mean = s*(1.f/64.f), d0 = v0-mean, d1 = v1-mean;
        float vs = d0*d0 + d1*d1;
        for (int o=16;o>0;o>>=1) vs += __shfl_xor_sync(~0u,vs,o);
        float rstd = rsqrtf(vs*(1.f/64.f) + 1e-5f);
        ts[k][lane]    = d0*rstd*nts[lane]    + ntb[lane];
        ts[k][lane+32] = d1*rstd*nts[lane+32] + ntb[lane+32];
    }
    __syncthreads();
    if (tid < 64) {
        float t2 = 0.f;
        for (int c = 0; c < 64; c++) { float v = ts[tid][c]; t2 = fmaf(v,v,t2); }
        float cv = cov[tid], c1 = 1.f/cv, c2 = 0.5f*c1;
        g_c1[tid] = c1; g_c2[tid] = c2;
        g_c0[tid] = logf(pi[tid]/sqrtf(cv)) - t2*c2;
    }
    __syncthreads();
    for (int j = 0; j < 8; j++) {
        int idx = tid + 256*j, c = idx>>5, l = idx&31;
        g_tsp[c*32+l] = make_float2(ts[l][c], ts[l+32][c]);
    }
}

__global__ __launch_bounds__(256)
void k_proj(const float* __restrict__ x, const float* __restrict__ w) {
    int b = blockIdx.y, n0 = blockIdx.x*128;
    __shared__ float Xs[16][128], Ws[64][20], xfs[128][65];
    int tid = threadIdx.x, tn = tid&31, tc = tid>>5;
    float acc[4][8];
    for (int q=0;q<4;q++) for (int r=0;r<8;r++) acc[q][r] = 0.f;
    const float* xb = x + ((size_t)b*CIN)*NN + n0;
    for (int it = 0; it < CIN/16; it++) {
        for (int j = 0; j < 2; j++) {
            int idx = tid + 256*j, r = idx>>5, c = (idx&31)<<2;
            *(float4*)&Xs[r][c] = *(const float4*)&xb[(it*16+r)*NN + c];
        }
        { int r = tid>>2, c = (tid&3)<<2;
          *(float4*)&Ws[r][c] = *(const float4*)&w[r*CIN + it*16 + c]; }
        __syncthreads();
        for (int ii = 0; ii < 16; ii++) {
            float xv[4], wv[8];
            for (int q=0;q<4;q++) xv[q] = Xs[ii][tn+32*q];
            for (int r=0;r<8;r++) wv[r] = Ws[tc+8*r][ii];
            for (int q=0;q<4;q++) for (int r=0;r<8;r++) acc[q][r] = fmaf(xv[q],wv[r],acc[q][r]);
        }
        __syncthreads();
    }
    for (int q=0;q<4;q++) for (int r=0;r<8;r++) xfs[tn+32*q][tc+8*r] = acc[q][r];
    __syncthreads();
    if (tid < 128) {
        float s = 0.f;
        for (int c = 0; c < 64; c++) { float v = xfs[tid][c]; s = fmaf(v,v,s); }
        g_x2[b*NN + n0 + tid] = s;
    }
    float* xfg = g_xf + (size_t)(b*NN+n0)*64;
    for (int j = 0; j < 32; j++) { int idx = tid + 256*j; xfg[idx] = xfs[idx>>6][idx&63]; }
}

__global__ __launch_bounds__(256)
void k_softmax(float* __restrict__ attn_out) {
    int b = blockIdx.y, n0 = blockIdx.x*32;
    __shared__ float xfs[32][64];
    __shared__ float2 tsp_s[64][32];
    __shared__ float attn_s[64][33], x2s[32], c0s[64], c1s[64], c2s[64];
    int tid = threadIdx.x;
    if (tid < 64) { c0s[tid]=g_c0[tid]; c1s[tid]=g_c1[tid]; c2s[tid]=g_c2[tid]; }
    if (tid < 32) x2s[tid] = g_x2[b*NN+n0+tid];
    { const float4* s = (const float4*)g_tsp; float4* d = (float4*)tsp_s;
      for (int j=0;j<4;j++) d[tid+256*j] = s[tid+256*j]; }
    { const float4* s = (const float4*)(g_xf + (size_t)(b*NN+n0)*64); float4* d = (float4*)xfs;
      d[tid] = s[tid]; d[tid+256] = s[tid+256]; }
    __syncthreads();
    int w = tid>>5, lane = tid&31;
    for (int q = 0; q < 4; q++) {
        int nl = w*4 + q;
        float x2v = x2s[nl], a0 = 0.f, a1 = 0.f;
        for (int c = 0; c < 64; c++) {
            float xc = xfs[nl][c]; float2 tv = tsp_s[c][lane];
            a0 = fmaf(xc, tv.x, a0); a1 = fmaf(xc, tv.y, a1);
        }
        float g0 = c0s[lane]    + a0*c1s[lane]    - x2v*c2s[lane];
        float g1 = c0s[lane+32] + a1*c1s[lane+32] - x2v*c2s[lane+32];
        float mx = fmaxf(g0, g1);
        for (int o=16;o>0;o>>=1) mx = fmaxf(mx, __shfl_xor_sync(~0u,mx,o));
        float e0 = __expf(g0-mx), e1 = __expf(g1-mx), s = e0+e1;
        for (int o=16;o>0;o>>=1) s += __shfl_xor_sync(~0u,s,o);
        float r = 1.f/s;
        attn_s[lane][nl] = e0*r; attn_s[lane+32][nl] = e1*r;
    }
    __syncthreads();
    if (tid < 64) {
        float cs = 0.f, ss = 0.f, ps = 0.f;
        for (int nl = 0; nl < 32; nl++) {
            float a = attn_s[tid][nl], ae = a + 1e-8f;
            ps += a; cs += ae; ss = fmaf(ae, x2s[nl], ss);
        }
        atomicAdd(&g_colsum[b*64+tid], cs);
        atomicAdd(&g_S[b*64+tid], ss);
        atomicAdd(&g_pisum[b*64+tid], ps);
    }
    float* pout = g_P + (size_t)(b*64)*NN + n0;
    float* aout = attn_out + (size_t)b*64*NN + n0;
    for (int j = 0; j < 8; j++) {
        int idx = tid + 256*j, k = idx>>5, ml = idx&31;
        float a = attn_s[k][ml];
        aout[(size_t)k*NN + ml] = a;
        pout[(size_t)k*NN + ml] = a + 1e-8f;
    }
}

__global__ __launch_bounds__(256)
void k_tnewgemm() {
    int b = blockIdx.y;
    __shared__ float Ps[64][33], Xs2[32][65];
    int tid = threadIdx.x, tx = tid&15, ty = tid>>4;
    float acc[4][4];
    for (int a=0;a<4;a++) for (int d=0;d<4;d++) acc[a][d] = 0.f;
    for (int st = 0; st < 8; st++) {
        int n0 = blockIdx.x*256 + st*32;
        for (int j = 0; j < 8; j++) {
            int idx = tid + 256*j;
            Ps[idx>>5][idx&31] = g_P[(size_t)(b*64 + (idx>>5))*NN + n0 + (idx&31)];
        }
        for (int j = 0; j < 8; j++) {
            int idx = tid + 256*j;
            Xs2[idx>>6][idx&63] = g_xf[((size_t)(b*NN+n0) + (idx>>6))*64 + (idx&63)];
        }
        __syncthreads();
        for (int nl = 0; nl < 32; nl++) {
            float kv[4], xv[4];
            for (int a=0;a<4;a++) kv[a] = Ps[ty+16*a][nl];
            for (int d=0;d<4;d++) xv[d] = Xs2[nl][tx+16*d];
            for (int a=0;a<4;a++) for (int d=0;d<4;d++) acc[a][d] = fmaf(kv[a],xv[d],acc[a][d]);
        }
        __syncthreads();
    }
    for (int a=0;a<4;a++) for (int d=0;d<4;d++)
        atomicAdd(&g_M[b*4096 + (ty+16*a)*64 + tx+16*d], acc[a][d]);
}

__global__ void k_stats(float* __restrict__ out_t, float* __restrict__ out_pi,
                        float* __restrict__ out_cov) {
    int b = blockIdx.x, k = threadIdx.x;
    float rc = 1.f/g_colsum[b*64+k], tn2 = 0.f;
    float* tout = out_t + (size_t)(b*64+k)*64;
    for (int c = 0; c < 64; c++) {
        float tv = g_M[b*4096 + k*64 + c]*rc;
        tout[c] = tv; tn2 = fmaf(tv,tv,tn2);
    }
    out_pi[b*64+k] = g_pisum[b*64+k]*(1.f/(float)NN);
    out_cov[b*64+k] = g_S[b*64+k]*rc - tn2;
}

__global__ void k_table() {
    int idx = blockIdx.x*256 + threadIdx.x;
    if (idx < HH*HH) {
        int di = idx/HH, dj = idx%HH;
        g_T[idx] = expf(-sqrtf((float)(di*di + dj*dj)));
    }
}

__global__ void k_mcol() {
    __shared__ float Ts[HH*HH], U[HH*HH];
    int tid = threadIdx.x;
    for (int i = tid; i < HH*HH; i += 256) Ts[i] = g_T[i];
    __syncthreads();
    for (int idx = tid; idx < HH*HH; idx += 256) {
        int di = idx/HH, jm = idx%HH; float s = 0.f;
        for (int j = 0; j < HH; j++) s += Ts[di*HH + abs(j-jm)];
        U[idx] = s;
    }
    __syncthreads();
    for (int idx = tid; idx < HH*HH; idx += 256) {
        int im = idx/HH, jm = idx%HH; float s = 0.f;
        for (int i = 0; i < HH; i++) s += U[abs(i-im)*HH + jm];
        g_rcol[idx] = 1.f/s;
    }
}

/* opB[m][n] = Amask[n][m] = T(n,m)*rcol[m], split hi/lo */
__global__ void k_buildB() {
    int m = blockIdx.y, n = blockIdx.x*256 + threadIdx.x;
    int mi = m/HH, mj = m - mi*HH, ni = n/HH, nj = n - ni*HH;
    float v = g_T[abs(ni-mi)*HH + abs(nj-mj)] * g_rcol[m];
    __nv_bfloat16 h = __float2bfloat16(v);
    size_t idx = (size_t)m*NN + n;
    g_Bh[idx] = h;
    g_Bl[idx] = __float2bfloat16(v - __bfloat162float(h));
}

/* split fp32 -> bf16 hi/lo (for P only) */
__global__ void k_conv(const float* __restrict__ src, __nv_bfloat16* __restrict__ hi,
                       __nv_bfloat16* __restrict__ lo) {
    int idx = blockIdx.x*256 + threadIdx.x;
    float v = src[idx];
    __nv_bfloat16 h = __float2bfloat16(v);
    hi[idx] = h;
    lo[idx] = __float2bfloat16(v - __bfloat162float(h));
}

/* ------------ HMMA GEMM + fused epilogues ------------
   MODE 0: C = A@opB^T  -> write bf16 split (oh, ol)
   MODE 1: C = A@opB^T, scale rows by 1/colsum, LayerNorm over K (64-row halves), write outp
   smem/stage bf16 units, row stride SA=40: AH@0 AL@5120 BH@10240 BL@15360; stage 20480 */
#define SA 40
#define STG 20480

template<int MODE>
__global__ __launch_bounds__(256, 1)
void k_hgemm(const __nv_bfloat16* __restrict__ Ah, const __nv_bfloat16* __restrict__ Al,
             __nv_bfloat16* __restrict__ oh, __nv_bfloat16* __restrict__ ol,
             float* __restrict__ outp, const float* __restrict__ pns,
             const float* __restrict__ pnb) {
    extern __shared__ __nv_bfloat16 sm[];
    int tid = threadIdx.x, wid = tid>>5, lane = tid&31;
    int g = lane>>2, tig = lane&3;
    int wm = wid&3, wn = wid>>2;
    int bm = blockIdx.y<<7, bn = blockIdx.x<<7;

    const __nv_bfloat16* gAh = Ah + (size_t)bm*NN;
    const __nv_bfloat16* gAl = Al + (size_t)bm*NN;
    const __nv_bfloat16* gBh = g_Bh + (size_t)bn*NN;
    const __nv_bfloat16* gBl = g_Bl + (size_t)bn*NN;

    float c[2][8][4];
#pragma unroll
    for (int i=0;i<2;i++)
#pragma unroll
        for (int j=0;j<8;j++)
#pragma unroll
            for (int q=0;q<4;q++) c[i][j][q] = 0.f;

    int lr = tid>>2, lc = (tid&3)*8;
    unsigned int smbase = smem_u32(sm);

    /* ldmatrix lane address components */
    int laneA_row = lane & 15;
    int laneA_k   = (lane >> 4) << 3;
    int tB = lane >> 3;
    int laneB_row = ((tB & 1) << 3) + (lane & 7);
    int laneB_k   = (tB & 2) << 2;

    auto cp_load = [&](int ch, int st) {
        unsigned int sb = smbase + st*STG*2;
#pragma unroll
        for (int p = 0; p < 2; p++) {
            int row = lr + p*64;
            size_t go = (size_t)row*NN + ch*32 + lc;
            unsigned int so = (unsigned int)((row*SA + lc)*2);
            CP16(sb + 0u*10240 + so, (const void*)(gAh + go));
            CP16(sb + 1u*10240 + so, (const void*)(gAl + go));
            CP16(sb + 2u*10240 + so, (const void*)(gBh + go));
            CP16(sb + 3u*10240 + so, (const void*)(gBl + go));
        }
    };

    cp_load(0, 0);
    CP_COMMIT();
    CP_WAIT0();
    __syncthreads();

    for (int ch = 0; ch < 72; ch++) {
        int cur = ch & 1;
        if (ch + 1 < 72) { cp_load(ch+1, cur^1); CP_COMMIT(); }

        unsigned int sb2 = smbase + cur*(STG*2);
#pragma unroll
        for (int kk = 0; kk < 2; kk++) {
            int bk = kk*16;
            unsigned ah[2][4], al[2][4], bh[8][2], bl[8][2];
#pragma unroll
            for (int tm = 0; tm < 2; tm++) {
                unsigned uA = sb2 + (unsigned)(((wm*32 + tm*16 + laneA_row)*SA + bk + laneA_k)*2);
                LDSM4(ah[tm][0], ah[tm][1], ah[tm][2], ah[tm][3], uA);
                LDSM4(al[tm][0], al[tm][1], al[tm][2], al[tm][3], uA + 10240u);
            }
#pragma unroll
            for (int tnp = 0; tnp < 4; tnp++) {
                unsigned uB = sb2 + 20480u + (unsigned)(((wn*64 + tnp*16 + laneB_row)*SA + bk + laneB_k)*2);
                unsigned b0, b1, b2, b3;
                LDSM4(b0, b1, b2, b3, uB);
                bh[2*tnp][0] = b0; bh[2*tnp][1] = b2;
                bh[2*tnp+1][0] = b1; bh[2*tnp+1][1] = b3;
                LDSM4(b0, b1, b2, b3, uB + 10240u);
                bl[2*tnp][0] = b0; bl[2*tnp][1] = b2;
                bl[2*tnp+1][0] = b1; bl[2*tnp+1][1] = b3;
            }
#pragma unroll
            for (int tn = 0; tn < 8; tn++)
#pragma unroll
                for (int tm = 0; tm < 2; tm++) {
                    mma16816(c[tm][tn], ah[tm], bh[tn]);
                    mma16816(c[tm][tn], ah[tm], bl[tn]);
                    mma16816(c[tm][tn], al[tm], bh[tn]);
                }
        }
        if (ch + 1 < 72) CP_WAIT0();
        __syncthreads();
    }

    if (MODE == 0) {
        /* write bf16 split directly */
#pragma unroll
        for (int tm = 0; tm < 2; tm++) {
            int r0 = bm + wm*32 + tm*16 + g;
#pragma unroll
            for (int tn = 0; tn < 8; tn++) {
                int col = bn + wn*64 + tn*8 + 2*tig;
#pragma unroll
                for (int half = 0; half < 2; half++) {
                    int rr = r0 + half*8;
                    float v0 = c[tm][tn][2*half], v1 = c[tm][tn][2*half+1];
                    __nv_bfloat16 h0 = __float2bfloat16(v0), h1 = __float2bfloat16(v1);
                    __nv_bfloat16 l0 = __float2bfloat16(v0 - __bfloat162float(h0));
                    __nv_bfloat16 l1 = __float2bfloat16(v1 - __bfloat162float(h1));
                    *(__nv_bfloat162*)&oh[(size_t)rr*NN + col] = __nv_bfloat162(h0, h1);
                    *(__nv_bfloat162*)&ol[(size_t)rr*NN + col] = __nv_bfloat162(l0, l1);
                }
            }
        }
    } else {
        /* fused: scale by 1/colsum, LN over K within 64-row halves, write outp */
        float* ft    = (float*)sm;           /* [128][129] */
        float* rcs_s = ft + 128*129;
        float* mean_s= rcs_s + 128;          /* [2][128] */
        float* rstd_s= mean_s + 256;         /* [2][128] */
        float* sc_s  = rstd_s + 256;         /* [64] */
        float* bi_s  = sc_s + 64;            /* [64] */
        if (tid < 128) rcs_s[tid] = 1.f / g_colsum[bm + tid];
        if (tid < 64) { sc_s[tid] = pns[tid]; bi_s[tid] = pnb[tid]; }
        __syncthreads();
#pragma unroll
        for (int tm = 0; tm < 2; tm++) {
            int row0 = wm*32 + tm*16 + g;
#pragma unroll
            for (int tn = 0; tn < 8; tn++) {
                int col0 = wn*64 + tn*8 + 2*tig;
#pragma unroll
                for (int half = 0; half < 2; half++) {
                    int rr = row0 + half*8;
                    float rc = rcs_s[rr];
                    ft[rr*129 + col0]     = c[tm][tn][2*half]   * rc;
                    ft[rr*129 + col0 + 1] = c[tm][tn][2*half+1] * rc;
                }
            }
        }
        __syncthreads();
        {
            int col = tid & 127, bh2 = tid >> 7;
            const float* base = ft + (bh2*64)*129 + col;
            float s = 0.f;
#pragma unroll 8
            for (int k = 0; k < 64; k++) s += base[k*129];
            float mean = s * (1.f/64.f);
            float var = 0.f;
#pragma unroll 8
            for (int k = 0; k < 64; k++) { float d = base[k*129] - mean; var = fmaf(d, d, var); }
            mean_s[tid] = mean;
            rstd_s[tid] = rsqrtf(var * (1.f/64.f) + 1e-5f);
        }
        __syncthreads();
        for (int j = 0; j < 64; j++) {
            int idx = tid + 256*j;
            int row = idx >> 7, col = idx & 127;
            int bh2 = row >> 6, k = row & 63;
            float v = ft[row*129 + col];
            float o = (v - mean_s[bh2*128 + col]) * rstd_s[bh2*128 + col] * sc_s[k] + bi_s[k];
            outp[(size_t)(bm + row)*NN + bn + col] = o;
        }
    }
}

extern "C" void kernel_launch(void* const* d_in, const int* in_sizes, int n_in,
                              void* d_out, int out_size) {
    const float* x     = (const float*)d_in[0];
    const float* clus  = (const float*)d_in[1];
    const float* pi    = (const float*)d_in[2];
    const float* cov   = (const float*)d_in[3];
    const float* wproj = (const float*)d_in[4];
    const float* nts   = (const float*)d_in[5];
    const float* ntb   = (const float*)d_in[6];
    const float* pns   = (const float*)d_in[7];
    const float* pnb   = (const float*)d_in[8];
    float* out = (float*)d_out;
    float* out_outp = out;
    float* out_attn = out + 2359296;
    float* out_t    = out + 4718592;
    float* out_pi   = out + 4784128;
    float* out_cov  = out + 4785152;

    void *pP, *pPh, *pPl, *pYh, *pYl;
    cudaGetSymbolAddress(&pP,  g_P);
    cudaGetSymbolAddress(&pPh, g_Ph);
    cudaGetSymbolAddress(&pPl, g_Pl);
    cudaGetSymbolAddress(&pYh, g_Yh);
    cudaGetSymbolAddress(&pYl, g_Yl);

    cudaFuncSetAttribute(k_hgemm<0>, cudaFuncAttributeMaxDynamicSharedMemorySize, 81920);
    cudaFuncSetAttribute(k_hgemm<1>, cudaFuncAttributeMaxDynamicSharedMemorySize, 81920);

    k_zero<<<268, 256>>>();
    k_tmpl<<<1, 256>>>(clus, pi, cov, nts, ntb);
    k_proj<<<dim3(18, 16), 256>>>(x, wproj);
    k_softmax<<<dim3(72, 16), 256>>>(out_attn);
    k_tnewgemm<<<dim3(9, 16), 256>>>();
    k_stats<<<16, 64>>>(out_t, out_pi, out_cov);
    k_table<<<9, 256>>>();
    k_mcol<<<1, 256>>>();
    k_buildB<<<dim3(9, 2304), 256>>>();
    k_conv<<<9216, 256>>>((const float*)pP, (__nv_bfloat16*)pPh, (__nv_bfloat16*)pPl);
    k_hgemm<0><<<dim3(18, 8), 256, 81920>>>((const __nv_bfloat16*)pPh, (const __nv_bfloat16*)pPl,
                                            (__nv_bfloat16*)pYh, (__nv_bfloat16*)pYl,
                                            nullptr, nullptr, nullptr);
    k_hgemm<1><<<dim3(18, 8), 256, 81920>>>((const __nv_bfloat16*)pYh, (const __nv_bfloat16*)pYl,
                                            nullptr, nullptr, out_outp, pns, pnb);
}